// round 3
// baseline (speedup 1.0000x reference)
#include <cuda_runtime.h>
#include <cuda_bf16.h>
#include <math.h>

// Problem constants
#define BATCH 8
#define NPTS 4096
#define CH 128
#define KNN 9
#define MROWS (BATCH * NPTS)   // 32768
#define EPSBN 1e-5f

// GEMM tiling
#define BM 128
#define BN 128
#define BK 16
#define AS2_STRIDE (2 * BM + 8)   // duplicated-A shared stride (floats), pad kills fill conflicts
#define BS_STRIDE (BN + 4)

// ---------------- device scratch (no allocations allowed) ----------------
__device__ float g_S[(size_t)BATCH * NPTS * NPTS];   // 512 MB distance scores
__device__ float g_H[(size_t)MROWS * CH];            // h after fc1+BN
__device__ float g_Y[(size_t)MROWS * CH];            // pre-BN GEMM output (reused 3x)
__device__ float g_CAT[(size_t)MROWS * 2 * CH];      // [h, agg]
__device__ float g_HG[(size_t)MROWS * CH];           // after gcn BN+GELU
__device__ float g_rowsq[MROWS];
__device__ int   g_idx[MROWS * KNN];
__device__ float g_psum[256 * CH];
__device__ float g_psq[256 * CH];
__device__ float g_mean[CH];
__device__ float g_inv[CH];

// packed dual-FMA: d.lo += a.lo*b.lo ; d.hi += a.hi*b.hi  (SASS FFMA2)
__device__ __forceinline__ void ffma2(unsigned long long& d,
                                      unsigned long long a,
                                      unsigned long long b)
{
    asm("fma.rn.f32x2 %0, %1, %2, %3;" : "=l"(d) : "l"(a), "l"(b), "l"(d));
}

// ---------------- generic SGEMM: Out[M x 128] = A[M x Kd] @ W[Kd x 128] + bias ----------------
__global__ __launch_bounds__(256) void sgemm_bias_kernel(
    const float* __restrict__ A, const float* __restrict__ W,
    const float* __restrict__ bias, float* __restrict__ Out, int Kd)
{
    __shared__ float As2[BK][AS2_STRIDE];   // duplicated: As2[k][2m]=As2[k][2m+1]=A[m][k]
    __shared__ float Ws[BK][BN];

    const int tid = threadIdx.x;            // 256 threads = 16x16
    const int m0  = blockIdx.x * BM;
    const int tr  = tid / 16;
    const int tc  = tid % 16;

    unsigned long long acc2[8][4];
#pragma unroll
    for (int i = 0; i < 8; i++)
#pragma unroll
        for (int j = 0; j < 4; j++) acc2[i][j] = 0ull;

    for (int k0 = 0; k0 < Kd; k0 += BK) {
        // A tile: 128 rows x 16 k, stored transposed + duplicated
#pragma unroll
        for (int i = 0; i < 2; i++) {
            int lin  = tid + i * 256;       // 0..511 float4 slots
            int row  = lin >> 2;            // 4 float4 per row
            int col4 = lin & 3;
            float4 v = *(const float4*)(A + (size_t)(m0 + row) * Kd + k0 + col4 * 4);
            int k = col4 * 4;
            As2[k + 0][2 * row] = v.x; As2[k + 0][2 * row + 1] = v.x;
            As2[k + 1][2 * row] = v.y; As2[k + 1][2 * row + 1] = v.y;
            As2[k + 2][2 * row] = v.z; As2[k + 2][2 * row + 1] = v.z;
            As2[k + 3][2 * row] = v.w; As2[k + 3][2 * row + 1] = v.w;
        }
        // W tile: 16 rows x 128 cols, natural layout
#pragma unroll
        for (int i = 0; i < 2; i++) {
            int lin = tid + i * 256;        // 512 float4: 16 rows x 32 f4
            int row = lin >> 5;
            int c4  = lin & 31;
            *(float4*)&Ws[row][c4 * 4] =
                *(const float4*)(W + (size_t)(k0 + row) * 128 + c4 * 4);
        }
        __syncthreads();

#pragma unroll
        for (int k = 0; k < BK; k++) {
            unsigned long long a[8], b[4];
            const float* ap = &As2[k][tr * 16];
            const float* bp = &Ws[k][tc * 8];
            ulonglong2 t0 = *(const ulonglong2*)(ap);
            ulonglong2 t1 = *(const ulonglong2*)(ap + 4);
            ulonglong2 t2 = *(const ulonglong2*)(ap + 8);
            ulonglong2 t3 = *(const ulonglong2*)(ap + 12);
            a[0] = t0.x; a[1] = t0.y; a[2] = t1.x; a[3] = t1.y;
            a[4] = t2.x; a[5] = t2.y; a[6] = t3.x; a[7] = t3.y;
            ulonglong2 u0 = *(const ulonglong2*)(bp);
            ulonglong2 u1 = *(const ulonglong2*)(bp + 4);
            b[0] = u0.x; b[1] = u0.y; b[2] = u1.x; b[3] = u1.y;
#pragma unroll
            for (int i = 0; i < 8; i++)
#pragma unroll
                for (int j = 0; j < 4; j++) ffma2(acc2[i][j], a[i], b[j]);
        }
        __syncthreads();
    }

    float bv[8];
#pragma unroll
    for (int j = 0; j < 8; j++) bv[j] = bias[tc * 8 + j];
#pragma unroll
    for (int i = 0; i < 8; i++) {
        int m = m0 + tr * 8 + i;
        float* o = Out + (size_t)m * 128 + tc * 8;
        float v[8];
#pragma unroll
        for (int j = 0; j < 4; j++) {
            float2 p = *(float2*)&acc2[i][j];
            v[2 * j]     = p.x + bv[2 * j];
            v[2 * j + 1] = p.y + bv[2 * j + 1];
        }
        *(float4*)(o)     = *(float4*)(v);
        *(float4*)(o + 4) = *(float4*)(v + 4);
    }
}

// ---------------- distance GEMM (NT): s[b][i][j] = rowsq[b][j] - 2 * h_i . h_j ----------------
__global__ __launch_bounds__(256) void dist_kernel(
    const float* __restrict__ H, const float* __restrict__ rowsq,
    float* __restrict__ S)
{
    __shared__ float As2[BK][AS2_STRIDE];   // duplicated rows i
    __shared__ float Bs[BK][BS_STRIDE];     // rows j, natural

    const int tid = threadIdx.x;
    const int b   = blockIdx.z;
    const int i0  = blockIdx.y * BM;
    const int j0  = blockIdx.x * BN;
    const float* Hb = H + (size_t)b * NPTS * CH;
    const int tr = tid / 16;
    const int tc = tid % 16;

    unsigned long long acc2[8][4];
#pragma unroll
    for (int i = 0; i < 8; i++)
#pragma unroll
        for (int j = 0; j < 4; j++) acc2[i][j] = 0ull;

    for (int k0 = 0; k0 < CH; k0 += BK) {
#pragma unroll
        for (int i = 0; i < 2; i++) {
            int lin  = tid + i * 256;
            int row  = lin >> 2;
            int col4 = lin & 3;
            int k = col4 * 4;
            float4 va = *(const float4*)(Hb + (size_t)(i0 + row) * CH + k0 + col4 * 4);
            As2[k + 0][2 * row] = va.x; As2[k + 0][2 * row + 1] = va.x;
            As2[k + 1][2 * row] = va.y; As2[k + 1][2 * row + 1] = va.y;
            As2[k + 2][2 * row] = va.z; As2[k + 2][2 * row + 1] = va.z;
            As2[k + 3][2 * row] = va.w; As2[k + 3][2 * row + 1] = va.w;
            float4 vb = *(const float4*)(Hb + (size_t)(j0 + row) * CH + k0 + col4 * 4);
            Bs[k + 0][row] = vb.x;
            Bs[k + 1][row] = vb.y;
            Bs[k + 2][row] = vb.z;
            Bs[k + 3][row] = vb.w;
        }
        __syncthreads();

#pragma unroll
        for (int k = 0; k < BK; k++) {
            unsigned long long a[8], bb[4];
            const float* ap = &As2[k][tr * 16];
            const float* bp = &Bs[k][tc * 8];
            ulonglong2 t0 = *(const ulonglong2*)(ap);
            ulonglong2 t1 = *(const ulonglong2*)(ap + 4);
            ulonglong2 t2 = *(const ulonglong2*)(ap + 8);
            ulonglong2 t3 = *(const ulonglong2*)(ap + 12);
            a[0] = t0.x; a[1] = t0.y; a[2] = t1.x; a[3] = t1.y;
            a[4] = t2.x; a[5] = t2.y; a[6] = t3.x; a[7] = t3.y;
            ulonglong2 u0 = *(const ulonglong2*)(bp);
            ulonglong2 u1 = *(const ulonglong2*)(bp + 4);
            bb[0] = u0.x; bb[1] = u0.y; bb[2] = u1.x; bb[3] = u1.y;
#pragma unroll
            for (int i = 0; i < 8; i++)
#pragma unroll
                for (int j = 0; j < 4; j++) ffma2(acc2[i][j], a[i], bb[j]);
        }
        __syncthreads();
    }

    float sq[8];
#pragma unroll
    for (int j = 0; j < 8; j++) sq[j] = rowsq[b * NPTS + j0 + tc * 8 + j];

#pragma unroll
    for (int i = 0; i < 8; i++) {
        int gi = i0 + tr * 8 + i;
        float* o = S + ((size_t)b * NPTS + gi) * NPTS + j0 + tc * 8;
        float v[8];
#pragma unroll
        for (int j = 0; j < 4; j++) {
            float2 p = *(float2*)&acc2[i][j];
            v[2 * j]     = sq[2 * j]     - 2.0f * p.x;
            v[2 * j + 1] = sq[2 * j + 1] - 2.0f * p.y;
        }
        *(float4*)(o)     = *(float4*)(v);
        *(float4*)(o + 4) = *(float4*)(v + 4);
    }
}

// ---------------- top-9 smallest per row (tie -> lower index, like top_k) ----------------
__global__ __launch_bounds__(256) void topk_kernel(
    const float* __restrict__ S, int* __restrict__ Idx)
{
    const int row = blockIdx.x;                  // 0..MROWS-1
    const float* s = S + (size_t)row * NPTS;
    const int tid = threadIdx.x;                 // 256

    unsigned long long best[KNN];
#pragma unroll
    for (int q = 0; q < KNN; q++) best[q] = 0xFFFFFFFFFFFFFFFFull;

    for (int j = tid; j < NPTS; j += 256) {
        float v = s[j];
        unsigned int bits = __float_as_uint(v);
        unsigned int k32 = (bits & 0x80000000u) ? ~bits : (bits | 0x80000000u);
        unsigned long long key = ((unsigned long long)k32 << 32) | (unsigned int)j;
        if (key < best[KNN - 1]) {
            int p = KNN - 1;
            while (p > 0 && best[p - 1] > key) { best[p] = best[p - 1]; p--; }
            best[p] = key;
        }
    }

    __shared__ unsigned long long sm[256 * KNN];
#pragma unroll
    for (int q = 0; q < KNN; q++) sm[tid * KNN + q] = best[q];
    __syncthreads();

    for (int stride = 128; stride >= 1; stride >>= 1) {
        if (tid < stride) {
            unsigned long long* A  = &sm[tid * KNN];
            unsigned long long* Bp = &sm[(tid + stride) * KNN];
            unsigned long long out[KNN];
            int ia = 0, ib = 0;
#pragma unroll
            for (int q = 0; q < KNN; q++)
                out[q] = (A[ia] <= Bp[ib]) ? A[ia++] : Bp[ib++];
#pragma unroll
            for (int q = 0; q < KNN; q++) A[q] = out[q];
        }
        __syncthreads();
    }

    if (tid < KNN) Idx[row * KNN + tid] = (int)(sm[tid] & 0xFFFFFFFFull);
}

// ---------------- max-relative aggregation + concat ----------------
__global__ __launch_bounds__(128) void agg_cat_kernel(
    const float* __restrict__ H, const int* __restrict__ Idx,
    float* __restrict__ CAT)
{
    const int row = blockIdx.x;
    const int b   = row >> 12;            // /4096
    const int c   = threadIdx.x;          // 128

    __shared__ int nb[KNN];
    if (c < KNN) nb[c] = Idx[row * KNN + c];
    __syncthreads();

    const float hv = H[(size_t)row * CH + c];
    const float* Hb = H + (size_t)b * NPTS * CH;
    float m = -INFINITY;
#pragma unroll
    for (int k = 0; k < KNN; k++)
        m = fmaxf(m, Hb[(size_t)nb[k] * CH + c] - hv);

    CAT[(size_t)row * (2 * CH) + c]      = hv;
    CAT[(size_t)row * (2 * CH) + CH + c] = m;
}

// ---------------- deterministic column stats (mean / inv-std) ----------------
__global__ __launch_bounds__(128) void colstats1_kernel(
    const float* __restrict__ Y, float* __restrict__ psum, float* __restrict__ psq)
{
    const int blk = blockIdx.x;          // 256 blocks x 128 rows
    const int c   = threadIdx.x;
    const float* p = Y + (size_t)blk * 128 * CH + c;
    float s = 0.0f, ss = 0.0f;
    for (int r = 0; r < 128; r++) {
        float v = p[(size_t)r * CH];
        s += v; ss += v * v;
    }
    psum[blk * CH + c] = s;
    psq[blk * CH + c]  = ss;
}

__global__ __launch_bounds__(128) void colstats2_kernel(
    const float* __restrict__ psum, const float* __restrict__ psq,
    float* __restrict__ mean, float* __restrict__ inv)
{
    const int c = threadIdx.x;
    float s = 0.0f, ss = 0.0f;
    for (int i = 0; i < 256; i++) { s += psum[i * CH + c]; ss += psq[i * CH + c]; }
    const float m = s * (1.0f / (float)MROWS);
    const float v = ss * (1.0f / (float)MROWS) - m * m;
    mean[c] = m;
    inv[c]  = rsqrtf(v + EPSBN);
}

// ---------------- BN apply variants ----------------
__global__ __launch_bounds__(128) void bn_apply_rowsq_kernel(
    const float* __restrict__ Y, const float* __restrict__ mean,
    const float* __restrict__ inv, const float* __restrict__ g,
    const float* __restrict__ be, float* __restrict__ H,
    float* __restrict__ rowsq)
{
    const int row = blockIdx.x;
    const int c   = threadIdx.x;
    const float y = Y[(size_t)row * CH + c];
    const float h = g[c] * (y - mean[c]) * inv[c] + be[c];
    H[(size_t)row * CH + c] = h;

    __shared__ float red[CH];
    red[c] = h * h;
    __syncthreads();
    for (int s = 64; s >= 1; s >>= 1) {
        if (c < s) red[c] += red[c + s];
        __syncthreads();
    }
    if (c == 0) rowsq[row] = red[0];
}

__global__ __launch_bounds__(256) void bn_gelu_kernel(
    const float* __restrict__ Y, const float* __restrict__ mean,
    const float* __restrict__ inv, const float* __restrict__ g,
    const float* __restrict__ be, float* __restrict__ O)
{
    const int i = blockIdx.x * 256 + threadIdx.x;
    const int c = i & (CH - 1);
    const float y = Y[i];
    const float h = g[c] * (y - mean[c]) * inv[c] + be[c];
    O[i] = 0.5f * h * (1.0f + erff(h * 0.70710678118654752f));
}

__global__ __launch_bounds__(256) void bn_res_kernel(
    const float* __restrict__ Y, const float* __restrict__ mean,
    const float* __restrict__ inv, const float* __restrict__ g,
    const float* __restrict__ be, const float* __restrict__ x,
    float* __restrict__ out)
{
    const int i = blockIdx.x * 256 + threadIdx.x;
    const int c = i & (CH - 1);
    const float y = Y[i];
    const float h = g[c] * (y - mean[c]) * inv[c] + be[c];
    out[i] = h + x[i];
}

// ---------------- launch ----------------
extern "C" void kernel_launch(void* const* d_in, const int* in_sizes, int n_in,
                              void* d_out, int out_size)
{
    const float* x   = (const float*)d_in[0];
    const float* W1  = (const float*)d_in[1];
    const float* b1  = (const float*)d_in[2];
    const float* g1  = (const float*)d_in[3];
    const float* be1 = (const float*)d_in[4];
    const float* Wg  = (const float*)d_in[5];
    const float* bg  = (const float*)d_in[6];
    const float* gg  = (const float*)d_in[7];
    const float* beg = (const float*)d_in[8];
    const float* W2  = (const float*)d_in[9];
    const float* b2  = (const float*)d_in[10];
    const float* g2  = (const float*)d_in[11];
    const float* be2 = (const float*)d_in[12];
    float* out = (float*)d_out;

    float *pS, *pH, *pY, *pCAT, *pHG, *prowsq, *ppsum, *ppsq, *pmean, *pinv;
    int* pidx;
    cudaGetSymbolAddress((void**)&pS, g_S);
    cudaGetSymbolAddress((void**)&pH, g_H);
    cudaGetSymbolAddress((void**)&pY, g_Y);
    cudaGetSymbolAddress((void**)&pCAT, g_CAT);
    cudaGetSymbolAddress((void**)&pHG, g_HG);
    cudaGetSymbolAddress((void**)&prowsq, g_rowsq);
    cudaGetSymbolAddress((void**)&pidx, g_idx);
    cudaGetSymbolAddress((void**)&ppsum, g_psum);
    cudaGetSymbolAddress((void**)&ppsq, g_psq);
    cudaGetSymbolAddress((void**)&pmean, g_mean);
    cudaGetSymbolAddress((void**)&pinv, g_inv);

    // ---- fc1 + BN ----
    sgemm_bias_kernel<<<MROWS / BM, 256>>>(x, W1, b1, pY, CH);
    colstats1_kernel<<<256, 128>>>(pY, ppsum, ppsq);
    colstats2_kernel<<<1, 128>>>(ppsum, ppsq, pmean, pinv);
    bn_apply_rowsq_kernel<<<MROWS, 128>>>(pY, pmean, pinv, g1, be1, pH, prowsq);

    // ---- KNN ----
    dist_kernel<<<dim3(NPTS / BN, NPTS / BM, BATCH), 256>>>(pH, prowsq, pS);
    topk_kernel<<<MROWS, 256>>>(pS, pidx);
    agg_cat_kernel<<<MROWS, 128>>>(pH, pidx, pCAT);

    // ---- graph MLP: [h, agg] @ Wg + BN + GELU ----
    sgemm_bias_kernel<<<MROWS / BM, 256>>>(pCAT, Wg, bg, pY, 2 * CH);
    colstats1_kernel<<<256, 128>>>(pY, ppsum, ppsq);
    colstats2_kernel<<<1, 128>>>(ppsum, ppsq, pmean, pinv);
    bn_gelu_kernel<<<(MROWS * CH) / 256, 256>>>(pY, pmean, pinv, gg, beg, pHG);

    // ---- fc2 + BN + residual ----
    sgemm_bias_kernel<<<MROWS / BM, 256>>>(pHG, W2, b2, pY, CH);
    colstats1_kernel<<<256, 128>>>(pY, ppsum, ppsq);
    colstats2_kernel<<<1, 128>>>(ppsum, ppsq, pmean, pinv);
    bn_res_kernel<<<(MROWS * CH) / 256, 256>>>(pY, pmean, pinv, g2, be2, x, out);
}

// round 8
// speedup vs baseline: 1.2535x; 1.2535x over previous
#include <cuda_runtime.h>
#include <cuda_bf16.h>
#include <math.h>
#include <stdint.h>

// Problem constants
#define BATCH 8
#define NPTS 4096
#define CH 128
#define KNN 9
#define MROWS (BATCH * NPTS)   // 32768
#define EPSBN 1e-5f

// scalar GEMM tiling (fc1/gcn/fc2)
#define BM 128
#define BN 128
#define BK 16

// ---------------- device scratch (no allocations allowed) ----------------
__device__ float g_S[(size_t)BATCH * NPTS * NPTS];   // 512 MB distance scores
__device__ float g_H[(size_t)MROWS * CH];            // h after fc1+BN (fp32)
__device__ __nv_bfloat16 g_Hhi[(size_t)MROWS * CH];  // bf16 split hi
__device__ __nv_bfloat16 g_Hlo[(size_t)MROWS * CH];  // bf16 split lo
__device__ float g_Y[(size_t)MROWS * CH];            // pre-BN GEMM output (reused 3x)
__device__ float g_CAT[(size_t)MROWS * 2 * CH];      // [h, agg]
__device__ float g_HG[(size_t)MROWS * CH];           // after gcn BN+GELU
__device__ float g_rowsq[MROWS];
__device__ int   g_idx[MROWS * KNN];
__device__ float g_psum[256 * CH];
__device__ float g_psq[256 * CH];
__device__ float g_mean[CH];
__device__ float g_inv[CH];

// ================= mma.sync helpers (base sm_103 ISA, no 'a' features) =================
__device__ __forceinline__ uint32_t smem_u32(const void* p) {
    uint32_t a;
    asm("{ .reg .u64 t; cvta.to.shared.u64 t, %1; cvt.u32.u64 %0, t; }" : "=r"(a) : "l"(p));
    return a;
}

__device__ __forceinline__ void ldsm_x4(uint32_t* d, uint32_t addr) {
    asm volatile("ldmatrix.sync.aligned.m8n8.x4.shared.b16 {%0,%1,%2,%3}, [%4];"
                 : "=r"(d[0]), "=r"(d[1]), "=r"(d[2]), "=r"(d[3]) : "r"(addr));
}
__device__ __forceinline__ void ldsm_x2(uint32_t* d, uint32_t addr) {
    asm volatile("ldmatrix.sync.aligned.m8n8.x2.shared.b16 {%0,%1}, [%2];"
                 : "=r"(d[0]), "=r"(d[1]) : "r"(addr));
}
__device__ __forceinline__ void mma16816(float* c, const uint32_t* a, const uint32_t* b) {
    asm volatile(
        "mma.sync.aligned.m16n8k16.row.col.f32.bf16.bf16.f32 "
        "{%0,%1,%2,%3}, {%4,%5,%6,%7}, {%8,%9}, {%0,%1,%2,%3};"
        : "+f"(c[0]), "+f"(c[1]), "+f"(c[2]), "+f"(c[3])
        : "r"(a[0]), "r"(a[1]), "r"(a[2]), "r"(a[3]), "r"(b[0]), "r"(b[1]));
}

// swizzled byte offset inside a 128-row x 64-col bf16 tile (128B rows, 8x 16B chunks,
// chunk XOR row&7 -> conflict-free STS and LDSM)
__device__ __forceinline__ uint32_t swz(int row, int k) {
    return (uint32_t)(row * 128 + (((k >> 3) ^ (row & 7)) << 4) + (k & 7) * 2);
}

// ---------------- HMMA distance kernel ----------------
// s[b][i][j] = rowsq[b][j] - 2 * (hi_i+lo_i).(hi_j+lo_j)   (lo.lo dropped)
// smem: [0..512) sq tile, [512..66048) 4x 16KB tiles {A_hi, A_lo, B_hi, B_lo} (one 64-wide K phase)
#define DIST_SMEM 66048
__global__ __launch_bounds__(256) void dist_mma_kernel(
    const __nv_bfloat16* __restrict__ Hhi, const __nv_bfloat16* __restrict__ Hlo,
    const float* __restrict__ rowsq, float* __restrict__ S)
{
    extern __shared__ char smem[];
    float* s_sq = (float*)smem;
    char* tiles = smem + 512;
    const uint32_t tiles_u = smem_u32(tiles);

    const int tid = threadIdx.x;
    const int wid = tid >> 5;
    const int lid = tid & 31;
    const int b  = blockIdx.z;
    const int i0 = blockIdx.y * 128;
    const int j0 = blockIdx.x * 128;
    const int wi = wid >> 2;        // 0..1 : 64-row band
    const int wj = wid & 3;         // 0..3 : 32-col band

    const size_t rowA = (size_t)(b * NPTS + i0) * CH;
    const size_t rowB = (size_t)(b * NPTS + j0) * CH;

    float acc[4][4][4];
#pragma unroll
    for (int i = 0; i < 4; i++)
#pragma unroll
        for (int j = 0; j < 4; j++)
#pragma unroll
            for (int q = 0; q < 4; q++) acc[i][j][q] = 0.0f;

    if (tid < 128) s_sq[tid] = rowsq[b * NPTS + j0 + tid];

    // lane-derived ldmatrix address components
    const int a_quad = lid >> 3;            // 0..3
    const int a_rs   = lid & 7;
    const int b_half = (lid >> 3) & 1;      // 0..1
    const int b_rn   = lid & 7;

#pragma unroll
    for (int kp = 0; kp < 2; kp++) {
        if (kp) __syncthreads();
        // load 4 tiles: each 128 rows x 64 bf16 (8 chunks of 16B per row)
        for (int t = tid; t < 4096; t += 256) {
            int tile = t >> 10;             // 0..3
            int r    = (t >> 3) & 127;
            int c    = t & 7;               // 16B chunk
            const __nv_bfloat16* src = (tile & 1) ? Hlo : Hhi;
            size_t base = (tile < 2) ? rowA : rowB;
            uint32_t off = (uint32_t)(tile * 16384 + r * 128 + (((c ^ (r & 7))) << 4));
            *(uint4*)(tiles + off) =
                *(const uint4*)(src + base + (size_t)r * CH + kp * 64 + c * 8);
        }
        __syncthreads();

#pragma unroll
        for (int p = 0; p < 3; p++) {       // hi.hi, hi.lo, lo.hi
            const uint32_t Abase = tiles_u + ((p == 2) ? 16384u : 0u);
            const uint32_t Bbase = tiles_u + ((p == 1) ? 49152u : 32768u);
#pragma unroll
            for (int ks = 0; ks < 4; ks++) {
                const int k0 = ks * 16;
                uint32_t afr[4][4], bfr[4][2];
#pragma unroll
                for (int mt = 0; mt < 4; mt++) {
                    int row = wi * 64 + mt * 16 + ((a_quad & 1) << 3) + a_rs;
                    int kk  = k0 + ((a_quad >> 1) << 3);
                    ldsm_x4(afr[mt], Abase + (uint32_t)(row * 128 + (((kk >> 3) ^ (row & 7)) << 4)));
                }
#pragma unroll
                for (int nt = 0; nt < 4; nt++) {
                    int row = wj * 32 + nt * 8 + b_rn;
                    int kk  = k0 + (b_half << 3);
                    ldsm_x2(bfr[nt], Bbase + (uint32_t)(row * 128 + (((kk >> 3) ^ (row & 7)) << 4)));
                }
#pragma unroll
                for (int mt = 0; mt < 4; mt++)
#pragma unroll
                    for (int nt = 0; nt < 4; nt++)
                        mma16816(acc[mt][nt], afr[mt], bfr[nt]);
            }
        }
    }

    // epilogue: c-frag thread t -> rows {t/4, t/4+8}, cols {2(t%4), 2(t%4)+1}
    const int qr = lid >> 2;
    const int qc = (lid & 3) * 2;
#pragma unroll
    for (int mt = 0; mt < 4; mt++) {
#pragma unroll
        for (int nt = 0; nt < 4; nt++) {
            const int jl = wj * 32 + nt * 8 + qc;
            const float sq0 = s_sq[jl], sq1 = s_sq[jl + 1];
            const int gi = i0 + wi * 64 + mt * 16 + qr;
            float* o0 = S + ((size_t)(b * NPTS + gi)) * NPTS + j0 + jl;
            float* o1 = o0 + (size_t)8 * NPTS;
            float2 v0 = make_float2(sq0 - 2.0f * acc[mt][nt][0], sq1 - 2.0f * acc[mt][nt][1]);
            float2 v1 = make_float2(sq0 - 2.0f * acc[mt][nt][2], sq1 - 2.0f * acc[mt][nt][3]);
            *(float2*)o0 = v0;
            *(float2*)o1 = v1;
        }
    }
}

// ---------------- generic scalar SGEMM: Out[M x 128] = A[M x Kd] @ W[Kd x 128] + bias ----------------
__global__ __launch_bounds__(256) void sgemm_bias_kernel(
    const float* __restrict__ A, const float* __restrict__ W,
    const float* __restrict__ bias, float* __restrict__ Out, int Kd)
{
    __shared__ float As[BK][BM + 4];
    __shared__ float Ws[BK][BN];

    const int tid = threadIdx.x;            // 256 threads = 16x16
    const int m0  = blockIdx.x * BM;
    const int tr  = tid / 16;
    const int tc  = tid % 16;

    float acc[8][8];
#pragma unroll
    for (int i = 0; i < 8; i++)
#pragma unroll
        for (int j = 0; j < 8; j++) acc[i][j] = 0.0f;

    for (int k0 = 0; k0 < Kd; k0 += BK) {
#pragma unroll
        for (int i = 0; i < 2; i++) {
            int lin  = tid + i * 256;
            int row  = lin >> 2;
            int col4 = lin & 3;
            float4 v = *(const float4*)(A + (size_t)(m0 + row) * Kd + k0 + col4 * 4);
            As[col4 * 4 + 0][row] = v.x;
            As[col4 * 4 + 1][row] = v.y;
            As[col4 * 4 + 2][row] = v.z;
            As[col4 * 4 + 3][row] = v.w;
        }
#pragma unroll
        for (int i = 0; i < 2; i++) {
            int lin = tid + i * 256;
            int row = lin >> 5;
            int c4  = lin & 31;
            *(float4*)&Ws[row][c4 * 4] =
                *(const float4*)(W + (size_t)(k0 + row) * 128 + c4 * 4);
        }
        __syncthreads();

#pragma unroll
        for (int k = 0; k < BK; k++) {
            float a[8], b[8];
            *(float4*)(a)     = *(float4*)&As[k][tr * 8];
            *(float4*)(a + 4) = *(float4*)&As[k][tr * 8 + 4];
            *(float4*)(b)     = *(float4*)&Ws[k][tc * 8];
            *(float4*)(b + 4) = *(float4*)&Ws[k][tc * 8 + 4];
#pragma unroll
            for (int i = 0; i < 8; i++)
#pragma unroll
                for (int j = 0; j < 8; j++) acc[i][j] += a[i] * b[j];
        }
        __syncthreads();
    }

    float bv[8];
#pragma unroll
    for (int j = 0; j < 8; j++) bv[j] = bias[tc * 8 + j];
#pragma unroll
    for (int i = 0; i < 8; i++) {
        int m = m0 + tr * 8 + i;
        float* o = Out + (size_t)m * 128 + tc * 8;
#pragma unroll
        for (int j = 0; j < 8; j++) o[j] = acc[i][j] + bv[j];
    }
}

// ---------------- top-9 smallest per row (tie -> lower index, like top_k) ----------------
__global__ __launch_bounds__(256) void topk_kernel(
    const float* __restrict__ S, int* __restrict__ Idx)
{
    const int row = blockIdx.x;
    const float* s = S + (size_t)row * NPTS;
    const int tid = threadIdx.x;

    unsigned long long best[KNN];
#pragma unroll
    for (int q = 0; q < KNN; q++) best[q] = 0xFFFFFFFFFFFFFFFFull;

    for (int j = tid; j < NPTS; j += 256) {
        float v = s[j];
        unsigned int bits = __float_as_uint(v);
        unsigned int k32 = (bits & 0x80000000u) ? ~bits : (bits | 0x80000000u);
        unsigned long long key = ((unsigned long long)k32 << 32) | (unsigned int)j;
        if (key < best[KNN - 1]) {
            int p = KNN - 1;
            while (p > 0 && best[p - 1] > key) { best[p] = best[p - 1]; p--; }
            best[p] = key;
        }
    }

    __shared__ unsigned long long sm[256 * KNN];
#pragma unroll
    for (int q = 0; q < KNN; q++) sm[tid * KNN + q] = best[q];
    __syncthreads();

    for (int stride = 128; stride >= 1; stride >>= 1) {
        if (tid < stride) {
            unsigned long long* A  = &sm[tid * KNN];
            unsigned long long* Bp = &sm[(tid + stride) * KNN];
            unsigned long long out[KNN];
            int ia = 0, ib = 0;
#pragma unroll
            for (int q = 0; q < KNN; q++)
                out[q] = (A[ia] <= Bp[ib]) ? A[ia++] : Bp[ib++];
#pragma unroll
            for (int q = 0; q < KNN; q++) A[q] = out[q];
        }
        __syncthreads();
    }

    if (tid < KNN) Idx[row * KNN + tid] = (int)(sm[tid] & 0xFFFFFFFFull);
}

// ---------------- max-relative aggregation + concat ----------------
__global__ __launch_bounds__(128) void agg_cat_kernel(
    const float* __restrict__ H, const int* __restrict__ Idx,
    float* __restrict__ CAT)
{
    const int row = blockIdx.x;
    const int b   = row >> 12;
    const int c   = threadIdx.x;

    __shared__ int nb[KNN];
    if (c < KNN) nb[c] = Idx[row * KNN + c];
    __syncthreads();

    const float hv = H[(size_t)row * CH + c];
    const float* Hb = H + (size_t)b * NPTS * CH;
    float m = -INFINITY;
#pragma unroll
    for (int k = 0; k < KNN; k++)
        m = fmaxf(m, Hb[(size_t)nb[k] * CH + c] - hv);

    CAT[(size_t)row * (2 * CH) + c]      = hv;
    CAT[(size_t)row * (2 * CH) + CH + c] = m;
}

// ---------------- deterministic column stats (mean / inv-std) ----------------
__global__ __launch_bounds__(128) void colstats1_kernel(
    const float* __restrict__ Y, float* __restrict__ psum, float* __restrict__ psq)
{
    const int blk = blockIdx.x;
    const int c   = threadIdx.x;
    const float* p = Y + (size_t)blk * 128 * CH + c;
    float s = 0.0f, ss = 0.0f;
    for (int r = 0; r < 128; r++) {
        float v = p[(size_t)r * CH];
        s += v; ss += v * v;
    }
    psum[blk * CH + c] = s;
    psq[blk * CH + c]  = ss;
}

__global__ __launch_bounds__(128) void colstats2_kernel(
    const float* __restrict__ psum, const float* __restrict__ psq,
    float* __restrict__ mean, float* __restrict__ inv)
{
    const int c = threadIdx.x;
    float s = 0.0f, ss = 0.0f;
    for (int i = 0; i < 256; i++) { s += psum[i * CH + c]; ss += psq[i * CH + c]; }
    const float m = s * (1.0f / (float)MROWS);
    const float v = ss * (1.0f / (float)MROWS) - m * m;
    mean[c] = m;
    inv[c]  = rsqrtf(v + EPSBN);
}

// ---------------- BN apply + bf16 split + row sumsq ----------------
__global__ __launch_bounds__(128) void bn_apply_rowsq_kernel(
    const float* __restrict__ Y, const float* __restrict__ mean,
    const float* __restrict__ inv, const float* __restrict__ g,
    const float* __restrict__ be, float* __restrict__ H,
    __nv_bfloat16* __restrict__ Hhi, __nv_bfloat16* __restrict__ Hlo,
    float* __restrict__ rowsq)
{
    const int row = blockIdx.x;
    const int c   = threadIdx.x;
    const float y = Y[(size_t)row * CH + c];
    const float h = g[c] * (y - mean[c]) * inv[c] + be[c];
    H[(size_t)row * CH + c] = h;
    __nv_bfloat16 hi = __float2bfloat16(h);
    Hhi[(size_t)row * CH + c] = hi;
    Hlo[(size_t)row * CH + c] = __float2bfloat16(h - __bfloat162float(hi));

    __shared__ float red[CH];
    red[c] = h * h;
    __syncthreads();
    for (int s = 64; s >= 1; s >>= 1) {
        if (c < s) red[c] += red[c + s];
        __syncthreads();
    }
    if (c == 0) rowsq[row] = red[0];
}

__global__ __launch_bounds__(256) void bn_gelu_kernel(
    const float* __restrict__ Y, const float* __restrict__ mean,
    const float* __restrict__ inv, const float* __restrict__ g,
    const float* __restrict__ be, float* __restrict__ O)
{
    const int i = blockIdx.x * 256 + threadIdx.x;
    const int c = i & (CH - 1);
    const float y = Y[i];
    const float h = g[c] * (y - mean[c]) * inv[c] + be[c];
    O[i] = 0.5f * h * (1.0f + erff(h * 0.70710678118654752f));
}

__global__ __launch_bounds__(256) void bn_res_kernel(
    const float* __restrict__ Y, const float* __restrict__ mean,
    const float* __restrict__ inv, const float* __restrict__ g,
    const float* __restrict__ be, const float* __restrict__ x,
    float* __restrict__ out)
{
    const int i = blockIdx.x * 256 + threadIdx.x;
    const int c = i & (CH - 1);
    const float y = Y[i];
    const float h = g[c] * (y - mean[c]) * inv[c] + be[c];
    out[i] = h + x[i];
}

// ---------------- launch ----------------
extern "C" void kernel_launch(void* const* d_in, const int* in_sizes, int n_in,
                              void* d_out, int out_size)
{
    const float* x   = (const float*)d_in[0];
    const float* W1  = (const float*)d_in[1];
    const float* b1  = (const float*)d_in[2];
    const float* g1  = (const float*)d_in[3];
    const float* be1 = (const float*)d_in[4];
    const float* Wg  = (const float*)d_in[5];
    const float* bg  = (const float*)d_in[6];
    const float* gg  = (const float*)d_in[7];
    const float* beg = (const float*)d_in[8];
    const float* W2  = (const float*)d_in[9];
    const float* b2  = (const float*)d_in[10];
    const float* g2  = (const float*)d_in[11];
    const float* be2 = (const float*)d_in[12];
    float* out = (float*)d_out;

    float *pS, *pH, *pY, *pCAT, *pHG, *prowsq, *ppsum, *ppsq, *pmean, *pinv;
    __nv_bfloat16 *pHhi, *pHlo;
    int* pidx;
    cudaGetSymbolAddress((void**)&pS, g_S);
    cudaGetSymbolAddress((void**)&pH, g_H);
    cudaGetSymbolAddress((void**)&pHhi, g_Hhi);
    cudaGetSymbolAddress((void**)&pHlo, g_Hlo);
    cudaGetSymbolAddress((void**)&pY, g_Y);
    cudaGetSymbolAddress((void**)&pCAT, g_CAT);
    cudaGetSymbolAddress((void**)&pHG, g_HG);
    cudaGetSymbolAddress((void**)&prowsq, g_rowsq);
    cudaGetSymbolAddress((void**)&pidx, g_idx);
    cudaGetSymbolAddress((void**)&ppsum, g_psum);
    cudaGetSymbolAddress((void**)&ppsq, g_psq);
    cudaGetSymbolAddress((void**)&pmean, g_mean);
    cudaGetSymbolAddress((void**)&pinv, g_inv);

    cudaFuncSetAttribute(dist_mma_kernel, cudaFuncAttributeMaxDynamicSharedMemorySize, DIST_SMEM);

    // ---- fc1 + BN ----
    sgemm_bias_kernel<<<MROWS / BM, 256>>>(x, W1, b1, pY, CH);
    colstats1_kernel<<<256, 128>>>(pY, ppsum, ppsq);
    colstats2_kernel<<<1, 128>>>(ppsum, ppsq, pmean, pinv);
    bn_apply_rowsq_kernel<<<MROWS, 128>>>(pY, pmean, pinv, g1, be1, pH, pHhi, pHlo, prowsq);

    // ---- KNN (HMMA distances) ----
    dist_mma_kernel<<<dim3(NPTS / 128, NPTS / 128, BATCH), 256, DIST_SMEM>>>(pHhi, pHlo, prowsq, pS);
    topk_kernel<<<MROWS, 256>>>(pS, pidx);
    agg_cat_kernel<<<MROWS, 128>>>(pH, pidx, pCAT);

    // ---- graph MLP: [h, agg] @ Wg + BN + GELU ----
    sgemm_bias_kernel<<<MROWS / BM, 256>>>(pCAT, Wg, bg, pY, 2 * CH);
    colstats1_kernel<<<256, 128>>>(pY, ppsum, ppsq);
    colstats2_kernel<<<1, 128>>>(ppsum, ppsq, pmean, pinv);
    bn_gelu_kernel<<<(MROWS * CH) / 256, 256>>>(pY, pmean, pinv, gg, beg, pHG);

    // ---- fc2 + BN + residual ----
    sgemm_bias_kernel<<<MROWS / BM, 256>>>(pHG, W2, b2, pY, CH);
    colstats1_kernel<<<256, 128>>>(pY, ppsum, ppsq);
    colstats2_kernel<<<1, 128>>>(ppsum, ppsq, pmean, pinv);
    bn_res_kernel<<<(MROWS * CH) / 256, 256>>>(pY, pmean, pinv, g2, be2, x, out);
}

// round 10
// speedup vs baseline: 3.1797x; 2.5366x over previous
#include <cuda_runtime.h>
#include <cuda_bf16.h>
#include <math.h>
#include <stdint.h>

// Problem constants
#define BATCH 8
#define NPTS 4096
#define CH 128
#define KNN 9
#define MROWS (BATCH * NPTS)   // 32768
#define EPSBN 1e-5f

// scalar GEMM tiling (fc1/gcn/fc2)
#define BM 128
#define BN 128
#define BK 16

// ---------------- device scratch (no allocations allowed) ----------------
__device__ float g_S[(size_t)BATCH * NPTS * NPTS];   // 512 MB distance scores
__device__ float g_H[(size_t)MROWS * CH];            // h after fc1+BN (fp32)
__device__ __nv_bfloat16 g_Hhi[(size_t)MROWS * CH];  // bf16 split hi
__device__ __nv_bfloat16 g_Hlo[(size_t)MROWS * CH];  // bf16 split lo
__device__ float g_Y[(size_t)MROWS * CH];            // pre-BN GEMM output (reused 3x)
__device__ float g_CAT[(size_t)MROWS * 2 * CH];      // [h, agg]
__device__ float g_HG[(size_t)MROWS * CH];           // after gcn BN+GELU
__device__ float g_rowsq[MROWS];
__device__ int   g_idx[MROWS * KNN];
__device__ float g_psum[256 * CH];
__device__ float g_psq[256 * CH];
__device__ float g_mean[CH];
__device__ float g_inv[CH];

// ================= mma.sync helpers (base sm_103 ISA, no 'a' features) =================
__device__ __forceinline__ uint32_t smem_u32(const void* p) {
    uint32_t a;
    asm("{ .reg .u64 t; cvta.to.shared.u64 t, %1; cvt.u32.u64 %0, t; }" : "=r"(a) : "l"(p));
    return a;
}

__device__ __forceinline__ void ldsm_x4(uint32_t* d, uint32_t addr) {
    asm volatile("ldmatrix.sync.aligned.m8n8.x4.shared.b16 {%0,%1,%2,%3}, [%4];"
                 : "=r"(d[0]), "=r"(d[1]), "=r"(d[2]), "=r"(d[3]) : "r"(addr));
}
__device__ __forceinline__ void ldsm_x2(uint32_t* d, uint32_t addr) {
    asm volatile("ldmatrix.sync.aligned.m8n8.x2.shared.b16 {%0,%1}, [%2];"
                 : "=r"(d[0]), "=r"(d[1]) : "r"(addr));
}
__device__ __forceinline__ void mma16816(float* c, const uint32_t* a, const uint32_t* b) {
    asm volatile(
        "mma.sync.aligned.m16n8k16.row.col.f32.bf16.bf16.f32 "
        "{%0,%1,%2,%3}, {%4,%5,%6,%7}, {%8,%9}, {%0,%1,%2,%3};"
        : "+f"(c[0]), "+f"(c[1]), "+f"(c[2]), "+f"(c[3])
        : "r"(a[0]), "r"(a[1]), "r"(a[2]), "r"(a[3]), "r"(b[0]), "r"(b[1]));
}

// ---------------- HMMA distance kernel with symmetric-tile halving ----------------
// P(i,j) = hi_i.hi_j + hi_i.lo_j + lo_i.hi_j  (symmetric).  s(i,j) = sq[j] - 2 P(i,j).
// Compute only tiles bx >= by; write (by,bx) directly and (bx,by) via smem transpose.
// smem: [0..512) sq_j, [512..1024) sq_i, [1024..) tiles (65536) / transpose staging (66560)
#define DIST_SMEM (1024 + 128 * 130 * 4)
__global__ __launch_bounds__(256, 2) void dist_mma_kernel(
    const __nv_bfloat16* __restrict__ Hhi, const __nv_bfloat16* __restrict__ Hlo,
    const float* __restrict__ rowsq, float* __restrict__ S)
{
    extern __shared__ char smem[];
    float* s_sqj = (float*)smem;
    float* s_sqi = (float*)(smem + 512);
    char* tiles = smem + 1024;
    float* smemT = (float*)(smem + 1024);
    const uint32_t tiles_u = smem_u32(tiles);

    const int tid = threadIdx.x;
    const int wid = tid >> 5;
    const int lid = tid & 31;
    const int b  = blockIdx.z;

    // triangular map: t -> (by, bx) with bx >= by
    int rem = blockIdx.x, by = 0;
    while (rem >= 32 - by) { rem -= 32 - by; by++; }
    const int bx = by + rem;
    const int i0 = by * 128;
    const int j0 = bx * 128;

    const int wi = wid >> 2;        // 0..1 : 64-row band
    const int wj = wid & 3;         // 0..3 : 32-col band

    const size_t rowA = (size_t)(b * NPTS + i0) * CH;
    const size_t rowB = (size_t)(b * NPTS + j0) * CH;

    float acc[4][4][4];
#pragma unroll
    for (int i = 0; i < 4; i++)
#pragma unroll
        for (int j = 0; j < 4; j++)
#pragma unroll
            for (int q = 0; q < 4; q++) acc[i][j][q] = 0.0f;

    if (tid < 128) {
        s_sqj[tid] = rowsq[b * NPTS + j0 + tid];
        s_sqi[tid] = rowsq[b * NPTS + i0 + tid];
    }

    const int a_quad = lid >> 3;
    const int a_rs   = lid & 7;
    const int b_half = (lid >> 3) & 1;
    const int b_rn   = lid & 7;

#pragma unroll
    for (int kp = 0; kp < 2; kp++) {
        if (kp) __syncthreads();
        for (int t = tid; t < 4096; t += 256) {
            int tile = t >> 10;
            int r    = (t >> 3) & 127;
            int c    = t & 7;
            const __nv_bfloat16* src = (tile & 1) ? Hlo : Hhi;
            size_t base = (tile < 2) ? rowA : rowB;
            uint32_t off = (uint32_t)(tile * 16384 + r * 128 + (((c ^ (r & 7))) << 4));
            *(uint4*)(tiles + off) =
                *(const uint4*)(src + base + (size_t)r * CH + kp * 64 + c * 8);
        }
        __syncthreads();

#pragma unroll
        for (int p = 0; p < 3; p++) {       // hi.hi, hi.lo, lo.hi
            const uint32_t Abase = tiles_u + ((p == 2) ? 16384u : 0u);
            const uint32_t Bbase = tiles_u + ((p == 1) ? 49152u : 32768u);
#pragma unroll
            for (int ks = 0; ks < 4; ks++) {
                const int k0 = ks * 16;
                uint32_t afr[4][4], bfr[4][2];
#pragma unroll
                for (int mt = 0; mt < 4; mt++) {
                    int row = wi * 64 + mt * 16 + ((a_quad & 1) << 3) + a_rs;
                    int kk  = k0 + ((a_quad >> 1) << 3);
                    ldsm_x4(afr[mt], Abase + (uint32_t)(row * 128 + (((kk >> 3) ^ (row & 7)) << 4)));
                }
#pragma unroll
                for (int nt = 0; nt < 4; nt++) {
                    int row = wj * 32 + nt * 8 + b_rn;
                    int kk  = k0 + (b_half << 3);
                    ldsm_x2(bfr[nt], Bbase + (uint32_t)(row * 128 + (((kk >> 3) ^ (row & 7)) << 4)));
                }
#pragma unroll
                for (int mt = 0; mt < 4; mt++)
#pragma unroll
                    for (int nt = 0; nt < 4; nt++)
                        mma16816(acc[mt][nt], afr[mt], bfr[nt]);
            }
        }
    }

    // ---- direct write of tile (by, bx): s = sq_j - 2 P ----
    const int qr = lid >> 2;
    const int qc = (lid & 3) * 2;
#pragma unroll
    for (int mt = 0; mt < 4; mt++) {
#pragma unroll
        for (int nt = 0; nt < 4; nt++) {
            const int jl = wj * 32 + nt * 8 + qc;
            const float sq0 = s_sqj[jl], sq1 = s_sqj[jl + 1];
            const int gi = i0 + wi * 64 + mt * 16 + qr;
            float* o0 = S + ((size_t)(b * NPTS + gi)) * NPTS + j0 + jl;
            float* o1 = o0 + (size_t)8 * NPTS;
            *(float2*)o0 = make_float2(sq0 - 2.0f * acc[mt][nt][0], sq1 - 2.0f * acc[mt][nt][1]);
            *(float2*)o1 = make_float2(sq0 - 2.0f * acc[mt][nt][2], sq1 - 2.0f * acc[mt][nt][3]);
        }
    }

    // ---- mirrored tile (bx, by) via smem transpose: s = sq_i - 2 P^T ----
    if (bx != by) {
        __syncthreads();           // everyone done reading MMA tiles
        // stage raw dot products: smemT[r * 130 + c] = P(i0+r, j0+c)
#pragma unroll
        for (int mt = 0; mt < 4; mt++) {
#pragma unroll
            for (int nt = 0; nt < 4; nt++) {
                const int R = wi * 64 + mt * 16 + qr;
                const int C = wj * 32 + nt * 8 + qc;
                *(float2*)&smemT[R * 130 + C] = make_float2(acc[mt][nt][0], acc[mt][nt][1]);
                *(float2*)&smemT[(R + 8) * 130 + C] = make_float2(acc[mt][nt][2], acc[mt][nt][3]);
            }
        }
        __syncthreads();
        // warp w writes output rows r = w, w+8, ..., 120  (row j0+r, cols i0..i0+127)
        for (int r = wid; r < 128; r += 8) {
            float* o = S + ((size_t)(b * NPTS + j0 + r)) * NPTS + i0;
#pragma unroll
            for (int q = 0; q < 4; q++) {
                const int ii = lid + 32 * q;
                o[ii] = s_sqi[ii] - 2.0f * smemT[ii * 130 + r];
            }
        }
    }
}

// ---------------- SGEMM + fused column stats: Out = A @ W + bias, psum/psq per 128-row slab ----------------
__global__ __launch_bounds__(256) void sgemm_stats_kernel(
    const float* __restrict__ A, const float* __restrict__ W,
    const float* __restrict__ bias, float* __restrict__ Out,
    float* __restrict__ psum, float* __restrict__ psq, int Kd)
{
    __shared__ float sh[16 * 132 + 16 * 128];
    float (*As)[132] = (float(*)[132])sh;
    float (*Ws)[128] = (float(*)[128])(sh + 16 * 132);

    const int tid = threadIdx.x;            // 256 threads = 16x16
    const int m0  = blockIdx.x * BM;
    const int tr  = tid / 16;
    const int tc  = tid % 16;

    float acc[8][8];
#pragma unroll
    for (int i = 0; i < 8; i++)
#pragma unroll
        for (int j = 0; j < 8; j++) acc[i][j] = 0.0f;

    for (int k0 = 0; k0 < Kd; k0 += BK) {
#pragma unroll
        for (int i = 0; i < 2; i++) {
            int lin  = tid + i * 256;
            int row  = lin >> 2;
            int col4 = lin & 3;
            float4 v = *(const float4*)(A + (size_t)(m0 + row) * Kd + k0 + col4 * 4);
            As[col4 * 4 + 0][row] = v.x;
            As[col4 * 4 + 1][row] = v.y;
            As[col4 * 4 + 2][row] = v.z;
            As[col4 * 4 + 3][row] = v.w;
        }
#pragma unroll
        for (int i = 0; i < 2; i++) {
            int lin = tid + i * 256;
            int row = lin >> 5;
            int c4  = lin & 31;
            *(float4*)&Ws[row][c4 * 4] =
                *(const float4*)(W + (size_t)(k0 + row) * 128 + c4 * 4);
        }
        __syncthreads();

#pragma unroll
        for (int k = 0; k < BK; k++) {
            float a[8], b[8];
            *(float4*)(a)     = *(float4*)&As[k][tr * 8];
            *(float4*)(a + 4) = *(float4*)&As[k][tr * 8 + 4];
            *(float4*)(b)     = *(float4*)&Ws[k][tc * 8];
            *(float4*)(b + 4) = *(float4*)&Ws[k][tc * 8 + 4];
#pragma unroll
            for (int i = 0; i < 8; i++)
#pragma unroll
                for (int j = 0; j < 8; j++) acc[i][j] += a[i] * b[j];
        }
        __syncthreads();
    }

    float bv[8];
#pragma unroll
    for (int j = 0; j < 8; j++) bv[j] = bias[tc * 8 + j];
#pragma unroll
    for (int i = 0; i < 8; i++) {
        int m = m0 + tr * 8 + i;
        float* o = Out + (size_t)m * 128 + tc * 8;
#pragma unroll
        for (int j = 0; j < 8; j++) o[j] = acc[i][j] + bv[j];
    }

    // fused deterministic column stats over this block's 128 rows
    float ls[8], lq[8];
#pragma unroll
    for (int j = 0; j < 8; j++) { ls[j] = 0.0f; lq[j] = 0.0f; }
#pragma unroll
    for (int i = 0; i < 8; i++)
#pragma unroll
        for (int j = 0; j < 8; j++) {
            float y = acc[i][j] + bv[j];
            ls[j] += y; lq[j] += y * y;
        }
    // reuse sh: [0..2048) sums, [2048..4096) sqs  (last loop's __syncthreads guards reuse)
#pragma unroll
    for (int j = 0; j < 8; j++) {
        sh[tr * 128 + tc * 8 + j]        = ls[j];
        sh[2048 + tr * 128 + tc * 8 + j] = lq[j];
    }
    __syncthreads();
    if (tid < 128) {
        float s = 0.0f, q = 0.0f;
#pragma unroll
        for (int r = 0; r < 16; r++) {
            s += sh[r * 128 + tid];
            q += sh[2048 + r * 128 + tid];
        }
        psum[blockIdx.x * CH + tid] = s;
        psq[blockIdx.x * CH + tid]  = q;
    }
}

// ---------------- branchless top-9 (sorting networks, tie -> lower index) ----------------
#define CEk(i,j) { unsigned long long a_ = kk[i], b_ = kk[j]; bool p_ = a_ < b_; \
                   kk[i] = p_ ? a_ : b_; kk[j] = p_ ? b_ : a_; }
#define SORT16() do { \
    CEk(0,1) CEk(2,3) CEk(4,5) CEk(6,7) CEk(8,9) CEk(10,11) CEk(12,13) CEk(14,15) \
    CEk(0,2) CEk(1,3) CEk(4,6) CEk(5,7) CEk(8,10) CEk(9,11) CEk(12,14) CEk(13,15) \
    CEk(1,2) CEk(5,6) CEk(9,10) CEk(13,14) \
    CEk(0,4) CEk(1,5) CEk(2,6) CEk(3,7) CEk(8,12) CEk(9,13) CEk(10,14) CEk(11,15) \
    CEk(2,4) CEk(3,5) CEk(10,12) CEk(11,13) \
    CEk(1,2) CEk(3,4) CEk(5,6) CEk(9,10) CEk(11,12) CEk(13,14) \
    CEk(0,8) CEk(1,9) CEk(2,10) CEk(3,11) CEk(4,12) CEk(5,13) CEk(6,14) CEk(7,15) \
    CEk(4,8) CEk(5,9) CEk(6,10) CEk(7,11) \
    CEk(2,4) CEk(3,5) CEk(6,8) CEk(7,9) CEk(10,12) CEk(11,13) \
    CEk(1,2) CEk(3,4) CEk(5,6) CEk(7,8) CEk(9,10) CEk(11,12) CEk(13,14) \
} while (0)
#define SORT9() do { \
    CEk(0,1) CEk(2,3) CEk(4,5) CEk(6,7) \
    CEk(0,2) CEk(1,3) CEk(4,6) CEk(5,7) \
    CEk(1,2) CEk(5,6) \
    CEk(0,4) CEk(1,5) CEk(2,6) CEk(3,7) \
    CEk(2,4) CEk(3,5) \
    CEk(1,2) CEk(3,4) CEk(5,6) \
    CEk(7,8) CEk(6,7) CEk(5,6) CEk(4,5) CEk(3,4) CEk(2,3) CEk(1,2) CEk(0,1) \
} while (0)

__global__ __launch_bounds__(256) void topk_kernel(
    const float* __restrict__ S, int* __restrict__ Idx)
{
    const int row = blockIdx.x;
    const int tid = threadIdx.x;
    const float4* s4 = (const float4*)(S + (size_t)row * NPTS + tid * 16);

    unsigned long long kk[16];
#pragma unroll
    for (int q = 0; q < 4; q++) {
        float4 v = s4[q];
        float f[4] = {v.x, v.y, v.z, v.w};
#pragma unroll
        for (int c = 0; c < 4; c++) {
            unsigned int bits = __float_as_uint(f[c]);
            unsigned int k32 = (bits & 0x80000000u) ? ~bits : (bits | 0x80000000u);
            kk[q * 4 + c] = ((unsigned long long)k32 << 32) | (unsigned int)(tid * 16 + q * 4 + c);
        }
    }
    SORT16();

    __shared__ unsigned long long sm[256 * KNN];
#pragma unroll
    for (int q = 0; q < KNN; q++) sm[tid * KNN + q] = kk[q];
    __syncthreads();

    for (int stride = 128; stride >= 1; stride >>= 1) {
        if (tid < stride) {
            const unsigned long long* Bp = &sm[(tid + stride) * KNN];
            unsigned long long bb[KNN];
#pragma unroll
            for (int q = 0; q < KNN; q++) bb[q] = Bp[q];
#pragma unroll
            for (int q = 0; q < KNN; q++) {
                unsigned long long cand = bb[KNN - 1 - q];
                if (cand < kk[q]) kk[q] = cand;   // min into kk
            }
            SORT9();
            if (stride > 1) {
#pragma unroll
                for (int q = 0; q < KNN; q++) sm[tid * KNN + q] = kk[q];
            }
        }
        __syncthreads();
    }

    if (tid == 0) {
#pragma unroll
        for (int q = 0; q < KNN; q++)
            Idx[row * KNN + q] = (int)(kk[q] & 0xFFFFFFFFull);
    }
}

// ---------------- max-relative aggregation + concat ----------------
__global__ __launch_bounds__(128) void agg_cat_kernel(
    const float* __restrict__ H, const int* __restrict__ Idx,
    float* __restrict__ CAT)
{
    const int row = blockIdx.x;
    const int b   = row >> 12;
    const int c   = threadIdx.x;

    __shared__ int nb[KNN];
    if (c < KNN) nb[c] = Idx[row * KNN + c];
    __syncthreads();

    const float hv = H[(size_t)row * CH + c];
    const float* Hb = H + (size_t)b * NPTS * CH;
    float m = -INFINITY;
#pragma unroll
    for (int k = 0; k < KNN; k++)
        m = fmaxf(m, Hb[(size_t)nb[k] * CH + c] - hv);

    CAT[(size_t)row * (2 * CH) + c]      = hv;
    CAT[(size_t)row * (2 * CH) + CH + c] = m;
}

// ---------------- final stats stage (mean / inv-std from 256 partials) ----------------
__global__ __launch_bounds__(128) void colstats2_kernel(
    const float* __restrict__ psum, const float* __restrict__ psq,
    float* __restrict__ mean, float* __restrict__ inv)
{
    const int c = threadIdx.x;
    float s = 0.0f, ss = 0.0f;
    for (int i = 0; i < 256; i++) { s += psum[i * CH + c]; ss += psq[i * CH + c]; }
    const float m = s * (1.0f / (float)MROWS);
    const float v = ss * (1.0f / (float)MROWS) - m * m;
    mean[c] = m;
    inv[c]  = rsqrtf(v + EPSBN);
}

// ---------------- BN apply + bf16 split + row sumsq ----------------
__global__ __launch_bounds__(128) void bn_apply_rowsq_kernel(
    const float* __restrict__ Y, const float* __restrict__ mean,
    const float* __restrict__ inv, const float* __restrict__ g,
    const float* __restrict__ be, float* __restrict__ H,
    __nv_bfloat16* __restrict__ Hhi, __nv_bfloat16* __restrict__ Hlo,
    float* __restrict__ rowsq)
{
    const int row = blockIdx.x;
    const int c   = threadIdx.x;
    const float y = Y[(size_t)row * CH + c];
    const float h = g[c] * (y - mean[c]) * inv[c] + be[c];
    H[(size_t)row * CH + c] = h;
    __nv_bfloat16 hi = __float2bfloat16(h);
    Hhi[(size_t)row * CH + c] = hi;
    Hlo[(size_t)row * CH + c] = __float2bfloat16(h - __bfloat162float(hi));

    __shared__ float red[CH];
    red[c] = h * h;
    __syncthreads();
    for (int s = 64; s >= 1; s >>= 1) {
        if (c < s) red[c] += red[c + s];
        __syncthreads();
    }
    if (c == 0) rowsq[row] = red[0];
}

__global__ __launch_bounds__(256) void bn_gelu_kernel(
    const float* __restrict__ Y, const float* __restrict__ mean,
    const float* __restrict__ inv, const float* __restrict__ g,
    const float* __restrict__ be, float* __restrict__ O)
{
    const int i = blockIdx.x * 256 + threadIdx.x;
    const int c = i & (CH - 1);
    const float y = Y[i];
    const float h = g[c] * (y - mean[c]) * inv[c] + be[c];
    O[i] = 0.5f * h * (1.0f + erff(h * 0.70710678118654752f));
}

__global__ __launch_bounds__(256) void bn_res_kernel(
    const float* __restrict__ Y, const float* __restrict__ mean,
    const float* __restrict__ inv, const float* __restrict__ g,
    const float* __restrict__ be, const float* __restrict__ x,
    float* __restrict__ out)
{
    const int i = blockIdx.x * 256 + threadIdx.x;
    const int c = i & (CH - 1);
    const float y = Y[i];
    const float h = g[c] * (y - mean[c]) * inv[c] + be[c];
    out[i] = h + x[i];
}

// ---------------- launch ----------------
extern "C" void kernel_launch(void* const* d_in, const int* in_sizes, int n_in,
                              void* d_out, int out_size)
{
    const float* x   = (const float*)d_in[0];
    const float* W1  = (const float*)d_in[1];
    const float* b1  = (const float*)d_in[2];
    const float* g1  = (const float*)d_in[3];
    const float* be1 = (const float*)d_in[4];
    const float* Wg  = (const float*)d_in[5];
    const float* bg  = (const float*)d_in[6];
    const float* gg  = (const float*)d_in[7];
    const float* beg = (const float*)d_in[8];
    const float* W2  = (const float*)d_in[9];
    const float* b2  = (const float*)d_in[10];
    const float* g2  = (const float*)d_in[11];
    const float* be2 = (const float*)d_in[12];
    float* out = (float*)d_out;

    float *pS, *pH, *pY, *pCAT, *pHG, *prowsq, *ppsum, *ppsq, *pmean, *pinv;
    __nv_bfloat16 *pHhi, *pHlo;
    int* pidx;
    cudaGetSymbolAddress((void**)&pS, g_S);
    cudaGetSymbolAddress((void**)&pH, g_H);
    cudaGetSymbolAddress((void**)&pHhi, g_Hhi);
    cudaGetSymbolAddress((void**)&pHlo, g_Hlo);
    cudaGetSymbolAddress((void**)&pY, g_Y);
    cudaGetSymbolAddress((void**)&pCAT, g_CAT);
    cudaGetSymbolAddress((void**)&pHG, g_HG);
    cudaGetSymbolAddress((void**)&prowsq, g_rowsq);
    cudaGetSymbolAddress((void**)&pidx, g_idx);
    cudaGetSymbolAddress((void**)&ppsum, g_psum);
    cudaGetSymbolAddress((void**)&ppsq, g_psq);
    cudaGetSymbolAddress((void**)&pmean, g_mean);
    cudaGetSymbolAddress((void**)&pinv, g_inv);

    cudaFuncSetAttribute(dist_mma_kernel, cudaFuncAttributeMaxDynamicSharedMemorySize, DIST_SMEM);

    // ---- fc1 + BN ----
    sgemm_stats_kernel<<<MROWS / BM, 256>>>(x, W1, b1, pY, ppsum, ppsq, CH);
    colstats2_kernel<<<1, 128>>>(ppsum, ppsq, pmean, pinv);
    bn_apply_rowsq_kernel<<<MROWS, 128>>>(pY, pmean, pinv, g1, be1, pH, pHhi, pHlo, prowsq);

    // ---- KNN (HMMA distances, symmetric tiles) ----
    dist_mma_kernel<<<dim3(528, 1, BATCH), 256, DIST_SMEM>>>(pHhi, pHlo, prowsq, pS);
    topk_kernel<<<MROWS, 256>>>(pS, pidx);
    agg_cat_kernel<<<MROWS, 128>>>(pH, pidx, pCAT);

    // ---- graph MLP: [h, agg] @ Wg + BN + GELU ----
    sgemm_stats_kernel<<<MROWS / BM, 256>>>(pCAT, Wg, bg, pY, ppsum, ppsq, 2 * CH);
    colstats2_kernel<<<1, 128>>>(ppsum, ppsq, pmean, pinv);
    bn_gelu_kernel<<<(MROWS * CH) / 256, 256>>>(pY, pmean, pinv, gg, beg, pHG);

    // ---- fc2 + BN + residual ----
    sgemm_stats_kernel<<<MROWS / BM, 256>>>(pHG, W2, b2, pY, ppsum, ppsq, CH);
    colstats2_kernel<<<1, 128>>>(ppsum, ppsq, pmean, pinv);
    bn_res_kernel<<<(MROWS * CH) / 256, 256>>>(pY, pmean, pinv, g2, be2, x, out);
}